// round 2
// baseline (speedup 1.0000x reference)
#include <cuda_runtime.h>
#include <math.h>

// Problem constants
#define Bb   8
#define Nn   64
#define Dd   128
#define Hh   4
#define DHh  32
#define Llay 3
#define FFf  512
#define Mm   (Bb*Nn*Nn)   // 32768 tokens

// ---------------- scratch (device globals; no runtime allocation) ----------------
__device__ float g_tok[Mm*Dd];            // 16 MB
__device__ float g_q  [Mm*Dd];
__device__ float g_k  [Mm*Dd];
__device__ float g_v1 [Mm*Dd];
__device__ float g_v2 [Mm*Dd];
__device__ float g_s  [Bb*Hh*Nn*Nn*Nn];   // [b,h,l,i,j]  33.5 MB
__device__ float g_o  [Mm*Dd];
__device__ float g_tmp[Mm*Dd];
__device__ float g_hid[Mm*FFf];           // 64 MB

// ---------------- embedding ----------------
// tok[b,i,j,:] = i==j ? x[b,i]@nW+nb : (mask ? ea[b,i,j]@eW+eb : no_edge)
__global__ void embed_kernel(const float* __restrict__ x, const float* __restrict__ ea,
                             const int* __restrict__ mask,
                             const float* __restrict__ nW, const float* __restrict__ nb,
                             const float* __restrict__ eW, const float* __restrict__ eb,
                             const float* __restrict__ noe)
{
    int m = blockIdx.x;           // token index (b,i,j)
    int d = threadIdx.x;          // 0..127
    int b = m >> 12;
    int i = (m >> 6) & 63;
    int j = m & 63;
    __shared__ float in_s[16];
    if (i == j) {
        if (d < 16) in_s[d] = x[(b*64+i)*16 + d];
        __syncthreads();
        float acc = nb[d];
        #pragma unroll
        for (int k = 0; k < 16; k++) acc += in_s[k] * nW[k*128 + d];
        g_tok[(size_t)m*128 + d] = acc;
    } else if (mask[m] != 0) {
        if (d < 8) in_s[d] = ea[(size_t)m*8 + d];
        __syncthreads();
        float acc = eb[d];
        #pragma unroll
        for (int k = 0; k < 8; k++) acc += in_s[k] * eW[k*128 + d];
        g_tok[(size_t)m*128 + d] = acc;
    } else {
        g_tok[(size_t)m*128 + d] = noe[d];
    }
}

// ---------------- SGEMM: 128x128 block tile, BK=8, 256 thr, 8x8/thread ----------------
template<int EPI>  // 0 = plain, 1 = bias + relu
__device__ __forceinline__ void sgemm_body(const float* __restrict__ A,
                                           const float* __restrict__ W,
                                           float* __restrict__ C,
                                           const float* __restrict__ bias,
                                           int Ndim, int Kdim, int m0, int n0)
{
    __shared__ float As[8][128];
    __shared__ float Bs[8][132];
    const int t  = threadIdx.x;
    const int tx = t & 15, ty = t >> 4;
    const int arow = t >> 1,  acol = (t & 1) * 4;   // A tile: 128 rows x 8 cols
    const int brow = t >> 5,  bcol = (t & 31) * 4;  // B tile: 8 rows x 128 cols

    float acc[8][8];
    #pragma unroll
    for (int i = 0; i < 8; i++)
        #pragma unroll
        for (int j = 0; j < 8; j++) acc[i][j] = 0.f;

    const float* Aptr = A + (size_t)(m0 + arow) * Kdim + acol;
    const float* Wptr = W + (size_t)brow * Ndim + n0 + bcol;

    for (int k0 = 0; k0 < Kdim; k0 += 8) {
        float4 av = *(const float4*)(Aptr + k0);
        As[acol+0][arow] = av.x;
        As[acol+1][arow] = av.y;
        As[acol+2][arow] = av.z;
        As[acol+3][arow] = av.w;
        float4 bv = *(const float4*)(Wptr + (size_t)k0 * Ndim);
        *(float4*)&Bs[brow][bcol] = bv;
        __syncthreads();
        #pragma unroll
        for (int k = 0; k < 8; k++) {
            float ra[8], rb[8];
            *(float4*)&ra[0] = *(const float4*)&As[k][ty*4];
            *(float4*)&ra[4] = *(const float4*)&As[k][64 + ty*4];
            *(float4*)&rb[0] = *(const float4*)&Bs[k][tx*4];
            *(float4*)&rb[4] = *(const float4*)&Bs[k][64 + tx*4];
            #pragma unroll
            for (int i = 0; i < 8; i++)
                #pragma unroll
                for (int j = 0; j < 8; j++)
                    acc[i][j] += ra[i] * rb[j];
        }
        __syncthreads();
    }

    #pragma unroll
    for (int ig = 0; ig < 2; ig++)
        #pragma unroll
        for (int ii = 0; ii < 4; ii++) {
            int m = m0 + ig*64 + ty*4 + ii;
            #pragma unroll
            for (int jg = 0; jg < 2; jg++) {
                int n = n0 + jg*64 + tx*4;
                float4 v;
                float* pv = (float*)&v;
                #pragma unroll
                for (int jj = 0; jj < 4; jj++) {
                    float val = acc[ig*4+ii][jg*4+jj];
                    if (EPI == 1) { val += bias[n + jj]; val = fmaxf(val, 0.f); }
                    pv[jj] = val;
                }
                *(float4*)(C + (size_t)m * Ndim + n) = v;
            }
        }
}

struct Ptr8 { const float* w[4]; float* c[4]; };

__global__ void __launch_bounds__(256) sgemm4_kernel(const float* A, Ptr8 p)
{
    sgemm_body<0>(A, p.w[blockIdx.z], p.c[blockIdx.z], nullptr, 128, 128,
                  blockIdx.y * 128, 0);
}
__global__ void __launch_bounds__(256) sgemm_kernel(const float* A, const float* W,
                                                    float* C, int Ndim, int Kdim)
{
    sgemm_body<0>(A, W, C, nullptr, Ndim, Kdim, blockIdx.y * 128, blockIdx.x * 128);
}
__global__ void __launch_bounds__(256) sgemm_bias_relu_kernel(const float* A, const float* W,
                                                              float* C, const float* bias,
                                                              int Ndim, int Kdim)
{
    sgemm_body<1>(A, W, C, bias, Ndim, Kdim, blockIdx.y * 128, blockIdx.x * 128);
}

// ---------------- attention scores: s[b,h,l,i,j] = Q_l @ K_l^T / sqrt(DH) ----------------
__global__ void __launch_bounds__(256) scores_kernel()
{
    int lin = blockIdx.x;          // (b,h,l)
    int l = lin & 63, h = (lin >> 6) & 3, b = lin >> 8;
    __shared__ float Qs[32][68];   // [d][i]
    __shared__ float Ks[32][68];   // [d][j]
    for (int e = threadIdx.x; e < 2048; e += 256) {
        int i = e >> 5, d = e & 31;
        Qs[d][i] = g_q[((size_t)((b*64+i)*64 + l))*128 + h*32 + d];
        Ks[d][i] = g_k[((size_t)((b*64+l)*64 + i))*128 + h*32 + d];
    }
    __syncthreads();
    int ti = threadIdx.x >> 4, tj = threadIdx.x & 15;
    int i0 = ti*4, j0 = tj*4;
    float acc[4][4];
    #pragma unroll
    for (int a = 0; a < 4; a++)
        #pragma unroll
        for (int c = 0; c < 4; c++) acc[a][c] = 0.f;
    #pragma unroll
    for (int d = 0; d < 32; d++) {
        float4 ra = *(const float4*)&Qs[d][i0];
        float4 rb = *(const float4*)&Ks[d][j0];
        float A[4] = {ra.x, ra.y, ra.z, ra.w};
        float Bv[4] = {rb.x, rb.y, rb.z, rb.w};
        #pragma unroll
        for (int ii = 0; ii < 4; ii++)
            #pragma unroll
            for (int jj = 0; jj < 4; jj++)
                acc[ii][jj] += A[ii] * Bv[jj];
    }
    const float isc = 0.17677669529663687f;   // 1/sqrt(32)
    float* sp = g_s + ((size_t)((b*4+h)*64 + l)) * 4096;
    #pragma unroll
    for (int ii = 0; ii < 4; ii++) {
        float4 v = make_float4(acc[ii][0]*isc, acc[ii][1]*isc, acc[ii][2]*isc, acc[ii][3]*isc);
        *(float4*)(sp + (i0+ii)*64 + j0) = v;
    }
}

// ---------------- softmax over l (axis 3) for each (b,h,i,j) ----------------
__global__ void __launch_bounds__(256) softmax_kernel()
{
    int lin = blockIdx.x;          // (b,h,i)
    int i = lin & 63, h = (lin >> 6) & 3, b = lin >> 8;
    __shared__ float sm[64][65];   // [l][j]
    float* base = g_s + ((size_t)(b*4+h))*262144 + i*64;
    for (int e = threadIdx.x; e < 4096; e += 256) {
        int l = e >> 6, j = e & 63;
        sm[l][j] = base[(size_t)l*4096 + j];
    }
    __syncthreads();
    if (threadIdx.x < 64) {
        int j = threadIdx.x;
        float mx = -1e30f;
        #pragma unroll 4
        for (int l = 0; l < 64; l++) mx = fmaxf(mx, sm[l][j]);
        float sum = 0.f;
        #pragma unroll 4
        for (int l = 0; l < 64; l++) { float e = __expf(sm[l][j] - mx); sm[l][j] = e; sum += e; }
        float inv = 1.f / sum;
        #pragma unroll 4
        for (int l = 0; l < 64; l++) sm[l][j] *= inv;
    }
    __syncthreads();
    for (int e = threadIdx.x; e < 4096; e += 256) {
        int l = e >> 6, j = e & 63;
        base[(size_t)l*4096 + j] = sm[l][j];
    }
}

// ---------------- combine: o[b,i,j,h,d] = sum_l a[b,h,l,i,j]*v1[b,i,l,h,d]*v2[b,l,j,h,d] ----------------
__global__ void __launch_bounds__(256) combine_kernel()
{
    int lin = blockIdx.x;          // (b,h,i)
    int i = lin & 63, h = (lin >> 6) & 3, b = lin >> 8;
    __shared__ float as_[64][65];      // [l][j]
    __shared__ float v1s[64][33];      // [l][d]
    __shared__ float v2s[2][64][33];   // double-buffered [j][d]
    const float* abase = g_s + ((size_t)(b*4+h))*262144 + i*64;
    for (int e = threadIdx.x; e < 4096; e += 256) {
        int l = e >> 6, j = e & 63;
        as_[l][j] = abase[(size_t)l*4096 + j];
    }
    for (int e = threadIdx.x; e < 2048; e += 256) {
        int l = e >> 5, d = e & 31;
        v1s[l][d] = g_v1[((size_t)((b*64+i)*64 + l))*128 + h*32 + d];
    }
    int j = threadIdx.x & 63, dg = threadIdx.x >> 6;  // dg in 0..3, 8 d's each
    float acc[8];
    #pragma unroll
    for (int k = 0; k < 8; k++) acc[k] = 0.f;

    for (int l = 0; l < 64; l++) {
        int buf = l & 1;
        for (int e = threadIdx.x; e < 2048; e += 256) {
            int jj = e >> 5, d = e & 31;
            v2s[buf][jj][d] = g_v2[((size_t)((b*64+l)*64 + jj))*128 + h*32 + d];
        }
        __syncthreads();
        float av = as_[l][j];
        const float* v1r = &v1s[l][dg*8];
        const float* v2r = &v2s[buf][j][dg*8];
        #pragma unroll
        for (int k = 0; k < 8; k++) acc[k] += av * v1r[k] * v2r[k];
    }
    float* op = g_o + ((size_t)((b*64+i)*64 + j))*128 + h*32 + dg*8;
    #pragma unroll
    for (int k = 0; k < 8; k++) op[k] = acc[k];
}

// ---------------- residual + bias + LayerNorm (in-place on g_tok) ----------------
__global__ void ln_kernel(const float* __restrict__ add, const float* __restrict__ bias,
                          const float* __restrict__ g, const float* __restrict__ bb)
{
    int row = blockIdx.x, d = threadIdx.x;
    size_t idx = (size_t)row*128 + d;
    float t = g_tok[idx] + add[idx] + bias[d];
    float s = t, s2 = t*t;
    #pragma unroll
    for (int o = 16; o; o >>= 1) {
        s  += __shfl_xor_sync(0xffffffffu, s,  o);
        s2 += __shfl_xor_sync(0xffffffffu, s2, o);
    }
    __shared__ float ws[4], ws2[4];
    if ((d & 31) == 0) { ws[d >> 5] = s; ws2[d >> 5] = s2; }
    __syncthreads();
    s  = ws[0] + ws[1] + ws[2] + ws[3];
    s2 = ws2[0] + ws2[1] + ws2[2] + ws2[3];
    float mean = s * (1.f/128.f);
    float var  = s2 * (1.f/128.f) - mean*mean;
    float r = rsqrtf(var + 1e-5f);
    g_tok[idx] = (t - mean) * r * g[d] + bb[d];
}

// ---------------- final head: out[b,n] = tok[b,n,n,:] @ Wout + bout ----------------
__global__ void out_kernel(const float* __restrict__ Wout, const float* __restrict__ bout,
                           float* __restrict__ out)
{
    int bn = blockIdx.x, d = threadIdx.x;
    int b = bn >> 6, n = bn & 63;
    float v = g_tok[((size_t)((b*64+n)*64 + n))*128 + d] * Wout[d];
    #pragma unroll
    for (int o = 16; o; o >>= 1) v += __shfl_xor_sync(0xffffffffu, v, o);
    __shared__ float ws[4];
    if ((d & 31) == 0) ws[d >> 5] = v;
    __syncthreads();
    if (d == 0) out[bn] = ws[0] + ws[1] + ws[2] + ws[3] + bout[0];
}

// ---------------- host orchestration ----------------
extern "C" void kernel_launch(void* const* d_in, const int* in_sizes, int n_in,
                              void* d_out, int out_size)
{
    const float* x    = (const float*)d_in[0];
    const float* ea   = (const float*)d_in[1];
    const int*   mask = (const int*)d_in[2];
    const float* nW   = (const float*)d_in[3];
    const float* nb   = (const float*)d_in[4];
    const float* eW   = (const float*)d_in[5];
    const float* eb   = (const float*)d_in[6];
    const float* noe  = (const float*)d_in[7];
    const float* Wq   = (const float*)d_in[8];
    const float* Wk   = (const float*)d_in[9];
    const float* Wv1  = (const float*)d_in[10];
    const float* Wv2  = (const float*)d_in[11];
    const float* Wo   = (const float*)d_in[12];
    const float* bo   = (const float*)d_in[13];
    const float* ln1g = (const float*)d_in[14];
    const float* ln1b = (const float*)d_in[15];
    const float* W1   = (const float*)d_in[16];
    const float* b1   = (const float*)d_in[17];
    const float* W2   = (const float*)d_in[18];
    const float* b2   = (const float*)d_in[19];
    const float* ln2g = (const float*)d_in[20];
    const float* ln2b = (const float*)d_in[21];
    const float* Wout = (const float*)d_in[22];
    const float* bout = (const float*)d_in[23];
    float* out = (float*)d_out;

    float *tok, *q, *k, *v1, *v2, *o, *tmp, *hid;
    cudaGetSymbolAddress((void**)&tok, g_tok);
    cudaGetSymbolAddress((void**)&q,   g_q);
    cudaGetSymbolAddress((void**)&k,   g_k);
    cudaGetSymbolAddress((void**)&v1,  g_v1);
    cudaGetSymbolAddress((void**)&v2,  g_v2);
    cudaGetSymbolAddress((void**)&o,   g_o);
    cudaGetSymbolAddress((void**)&tmp, g_tmp);
    cudaGetSymbolAddress((void**)&hid, g_hid);

    embed_kernel<<<Mm, 128>>>(x, ea, mask, nW, nb, eW, eb, noe);

    for (int l = 0; l < Llay; l++) {
        Ptr8 p;
        p.w[0] = Wq  + (size_t)l*128*128;
        p.w[1] = Wk  + (size_t)l*128*128;
        p.w[2] = Wv1 + (size_t)l*128*128;
        p.w[3] = Wv2 + (size_t)l*128*128;
        p.c[0] = q; p.c[1] = k; p.c[2] = v1; p.c[3] = v2;
        sgemm4_kernel<<<dim3(1, Mm/128, 4), 256>>>(tok, p);

        scores_kernel <<<Bb*Hh*Nn, 256>>>();
        softmax_kernel<<<Bb*Hh*Nn, 256>>>();
        combine_kernel<<<Bb*Hh*Nn, 256>>>();

        // tok = LN(tok + o@Wo + bo)
        sgemm_kernel<<<dim3(1, Mm/128), 256>>>(o, Wo + (size_t)l*128*128, tmp, 128, 128);
        ln_kernel<<<Mm, 128>>>(tmp, bo + l*128, ln1g + l*128, ln1b + l*128);

        // ff
        sgemm_bias_relu_kernel<<<dim3(FFf/128, Mm/128), 256>>>(tok, W1 + (size_t)l*128*512,
                                                               hid, b1 + l*512, 512, 128);
        sgemm_kernel<<<dim3(1, Mm/128), 256>>>(hid, W2 + (size_t)l*512*128, tmp, 128, 512);
        ln_kernel<<<Mm, 128>>>(tmp, b2 + l*128, ln2g + l*128, ln2b + l*128);
    }

    out_kernel<<<Bb*Nn, 128>>>(Wout, bout, out);
}

// round 3
// speedup vs baseline: 1.1038x; 1.1038x over previous
#include <cuda_runtime.h>
#include <math.h>

// Problem constants
#define Bb   8
#define Nn   64
#define Dd   128
#define Hh   4
#define DHh  32
#define Llay 3
#define FFf  512
#define Mm   (Bb*Nn*Nn)   // 32768 tokens

// ---------------- scratch (device globals; no runtime allocation) ----------------
__device__ float g_tok[Mm*Dd];            // 16 MB
__device__ float g_q  [Mm*Dd];
__device__ float g_k  [Mm*Dd];
__device__ float g_v1 [Mm*Dd];
__device__ float g_v2 [Mm*Dd];
__device__ float g_s  [Bb*Hh*Nn*Nn*Nn];   // [b,h,l,i,j]  33.5 MB
__device__ float g_o  [Mm*Dd];
__device__ float g_hid[Mm*FFf];           // 64 MB

// ---------------- embedding ----------------
__global__ void embed_kernel(const float* __restrict__ x, const float* __restrict__ ea,
                             const int* __restrict__ mask,
                             const float* __restrict__ nW, const float* __restrict__ nb,
                             const float* __restrict__ eW, const float* __restrict__ eb,
                             const float* __restrict__ noe)
{
    int m = blockIdx.x;           // token index (b,i,j)
    int d = threadIdx.x;          // 0..127
    int b = m >> 12;
    int i = (m >> 6) & 63;
    int j = m & 63;
    __shared__ float in_s[16];
    if (i == j) {
        if (d < 16) in_s[d] = x[(b*64+i)*16 + d];
        __syncthreads();
        float acc = nb[d];
        #pragma unroll
        for (int k = 0; k < 16; k++) acc += in_s[k] * nW[k*128 + d];
        g_tok[(size_t)m*128 + d] = acc;
    } else if (mask[m] != 0) {
        if (d < 8) in_s[d] = ea[(size_t)m*8 + d];
        __syncthreads();
        float acc = eb[d];
        #pragma unroll
        for (int k = 0; k < 8; k++) acc += in_s[k] * eW[k*128 + d];
        g_tok[(size_t)m*128 + d] = acc;
    } else {
        g_tok[(size_t)m*128 + d] = noe[d];
    }
}

// ---------------- SGEMM core: 128x128 tile, BK=16, double-buffered, 256 thr, 8x8/thread ----------------
// EPI: 0 = plain store to C
//      1 = bias + relu store to C
//      2 = C is tok: out = LN(tok_residual + acc + bias) written back to C (Ndim must be 128, n0=0)
template<int EPI>
__device__ __forceinline__ void sgemm_core(const float* __restrict__ A,
                                           const float* __restrict__ W,
                                           float* __restrict__ C,
                                           const float* __restrict__ bias,
                                           const float* __restrict__ gamma,
                                           const float* __restrict__ beta,
                                           int Ndim, int Kdim, int m0, int n0)
{
    __shared__ float As[2][16][128];
    __shared__ float Bs[2][16][132];
    const int t  = threadIdx.x;
    const int tx = t & 15, ty = t >> 4;
    const int arow = t >> 1,  acol = (t & 1) * 8;   // A tile: 128 rows x 16 cols, 8 floats/thread
    const int brow = t >> 5,  bcol = (t & 31) * 4;  // B tile: 16 rows x 128 cols, rows brow & brow+8

    const float* Aptr = A + (size_t)(m0 + arow) * Kdim + acol;
    const float* Wptr = W + (size_t)brow * Ndim + n0 + bcol;
    const size_t WrowStep = (size_t)8 * Ndim;

    float acc[8][8];
    #pragma unroll
    for (int i = 0; i < 8; i++)
        #pragma unroll
        for (int j = 0; j < 8; j++) acc[i][j] = 0.f;

    // prefetch block 0
    float4 a0 = *(const float4*)(Aptr);
    float4 a1 = *(const float4*)(Aptr + 4);
    float4 b0 = *(const float4*)(Wptr);
    float4 b1 = *(const float4*)(Wptr + WrowStep);
    {
        float av[8] = {a0.x,a0.y,a0.z,a0.w,a1.x,a1.y,a1.z,a1.w};
        #pragma unroll
        for (int c = 0; c < 8; c++) As[0][acol+c][arow] = av[c];
        *(float4*)&Bs[0][brow  ][bcol] = b0;
        *(float4*)&Bs[0][brow+8][bcol] = b1;
    }
    __syncthreads();

    const int nk = Kdim >> 4;
    for (int kb = 0; kb < nk; kb++) {
        const int cur = kb & 1;
        if (kb + 1 < nk) {
            const float* Ap = Aptr + (kb+1)*16;
            const float* Wp = Wptr + (size_t)(kb+1)*16*Ndim;
            a0 = *(const float4*)(Ap);
            a1 = *(const float4*)(Ap + 4);
            b0 = *(const float4*)(Wp);
            b1 = *(const float4*)(Wp + WrowStep);
        }
        #pragma unroll
        for (int k = 0; k < 16; k++) {
            float ra[8], rb[8];
            *(float4*)&ra[0] = *(const float4*)&As[cur][k][ty*4];
            *(float4*)&ra[4] = *(const float4*)&As[cur][k][64 + ty*4];
            *(float4*)&rb[0] = *(const float4*)&Bs[cur][k][tx*4];
            *(float4*)&rb[4] = *(const float4*)&Bs[cur][k][64 + tx*4];
            #pragma unroll
            for (int i = 0; i < 8; i++)
                #pragma unroll
                for (int j = 0; j < 8; j++)
                    acc[i][j] += ra[i] * rb[j];
        }
        if (kb + 1 < nk) {
            const int nxt = cur ^ 1;
            float av[8] = {a0.x,a0.y,a0.z,a0.w,a1.x,a1.y,a1.z,a1.w};
            #pragma unroll
            for (int c = 0; c < 8; c++) As[nxt][acol+c][arow] = av[c];
            *(float4*)&Bs[nxt][brow  ][bcol] = b0;
            *(float4*)&Bs[nxt][brow+8][bcol] = b1;
            __syncthreads();
        }
    }

    if (EPI == 2) {
        // fused residual + bias + LayerNorm; Ndim==128, n0==0, C == tok
        float bi[8], gm[8], bt[8];
        *(float4*)&bi[0] = *(const float4*)(bias  + tx*4);
        *(float4*)&bi[4] = *(const float4*)(bias  + 64 + tx*4);
        *(float4*)&gm[0] = *(const float4*)(gamma + tx*4);
        *(float4*)&gm[4] = *(const float4*)(gamma + 64 + tx*4);
        *(float4*)&bt[0] = *(const float4*)(beta  + tx*4);
        *(float4*)&bt[4] = *(const float4*)(beta  + 64 + tx*4);
        #pragma unroll
        for (int r = 0; r < 8; r++) {
            int m = m0 + (r >> 2)*64 + ty*4 + (r & 3);
            float res[8];
            *(float4*)&res[0] = *(const float4*)(C + (size_t)m*128 + tx*4);
            *(float4*)&res[4] = *(const float4*)(C + (size_t)m*128 + 64 + tx*4);
            float s = 0.f, s2 = 0.f;
            #pragma unroll
            for (int j = 0; j < 8; j++) {
                float v = acc[r][j] + res[j] + bi[j];
                acc[r][j] = v; s += v; s2 += v*v;
            }
            #pragma unroll
            for (int off = 8; off; off >>= 1) {
                s  += __shfl_xor_sync(0xffffffffu, s,  off);
                s2 += __shfl_xor_sync(0xffffffffu, s2, off);
            }
            float mean = s * (1.f/128.f);
            float var  = s2 * (1.f/128.f) - mean*mean;
            float rr = rsqrtf(var + 1e-5f);
            float o[8];
            #pragma unroll
            for (int j = 0; j < 8; j++) o[j] = (acc[r][j] - mean) * rr * gm[j] + bt[j];
            *(float4*)(C + (size_t)m*128 + tx*4)      = *(float4*)&o[0];
            *(float4*)(C + (size_t)m*128 + 64 + tx*4) = *(float4*)&o[4];
        }
    } else {
        #pragma unroll
        for (int ig = 0; ig < 2; ig++)
            #pragma unroll
            for (int ii = 0; ii < 4; ii++) {
                int m = m0 + ig*64 + ty*4 + ii;
                #pragma unroll
                for (int jg = 0; jg < 2; jg++) {
                    int n = n0 + jg*64 + tx*4;
                    float4 v;
                    float* pv = (float*)&v;
                    #pragma unroll
                    for (int jj = 0; jj < 4; jj++) {
                        float val = acc[ig*4+ii][jg*4+jj];
                        if (EPI == 1) { val += bias[n + jj]; val = fmaxf(val, 0.f); }
                        pv[jj] = val;
                    }
                    *(float4*)(C + (size_t)m * Ndim + n) = v;
                }
            }
    }
}

struct Ptr8 { const float* w[4]; float* c[4]; };

__global__ void __launch_bounds__(256) sgemm4_kernel(const float* A, Ptr8 p)
{
    sgemm_core<0>(A, p.w[blockIdx.z], p.c[blockIdx.z], nullptr, nullptr, nullptr,
                  128, 128, blockIdx.y * 128, 0);
}
__global__ void __launch_bounds__(256) sgemm_bias_relu_kernel(const float* A, const float* W,
                                                              float* C, const float* bias,
                                                              int Ndim, int Kdim)
{
    sgemm_core<1>(A, W, C, bias, nullptr, nullptr, Ndim, Kdim,
                  blockIdx.y * 128, blockIdx.x * 128);
}
__global__ void __launch_bounds__(256) sgemm_ln_kernel(const float* A, const float* W,
                                                       float* TOK, const float* bias,
                                                       const float* gamma, const float* beta,
                                                       int Kdim)
{
    sgemm_core<2>(A, W, TOK, bias, gamma, beta, 128, Kdim, blockIdx.y * 128, 0);
}

// ---------------- attention scores: s[b,h,l,i,j] = Q_l @ K_l^T / sqrt(DH) ----------------
__global__ void __launch_bounds__(256) scores_kernel()
{
    int lin = blockIdx.x;          // (b,h,l)
    int l = lin & 63, h = (lin >> 6) & 3, b = lin >> 8;
    __shared__ float Qs[32][68];   // [d][i]
    __shared__ float Ks[32][68];   // [d][j]
    for (int e = threadIdx.x; e < 2048; e += 256) {
        int i = e >> 5, d = e & 31;
        Qs[d][i] = g_q[((size_t)((b*64+i)*64 + l))*128 + h*32 + d];
        Ks[d][i] = g_k[((size_t)((b*64+l)*64 + i))*128 + h*32 + d];
    }
    __syncthreads();
    int ti = threadIdx.x >> 4, tj = threadIdx.x & 15;
    int i0 = ti*4, j0 = tj*4;
    float acc[4][4];
    #pragma unroll
    for (int a = 0; a < 4; a++)
        #pragma unroll
        for (int c = 0; c < 4; c++) acc[a][c] = 0.f;
    #pragma unroll
    for (int d = 0; d < 32; d++) {
        float4 ra = *(const float4*)&Qs[d][i0];
        float4 rb = *(const float4*)&Ks[d][j0];
        float A[4] = {ra.x, ra.y, ra.z, ra.w};
        float Bv[4] = {rb.x, rb.y, rb.z, rb.w};
        #pragma unroll
        for (int ii = 0; ii < 4; ii++)
            #pragma unroll
            for (int jj = 0; jj < 4; jj++)
                acc[ii][jj] += A[ii] * Bv[jj];
    }
    const float isc = 0.17677669529663687f;   // 1/sqrt(32)
    float* sp = g_s + ((size_t)((b*4+h)*64 + l)) * 4096;
    #pragma unroll
    for (int ii = 0; ii < 4; ii++) {
        float4 v = make_float4(acc[ii][0]*isc, acc[ii][1]*isc, acc[ii][2]*isc, acc[ii][3]*isc);
        *(float4*)(sp + (i0+ii)*64 + j0) = v;
    }
}

// ---------------- softmax over l (axis 3): parallel over all 256 threads ----------------
__global__ void __launch_bounds__(256) softmax_kernel()
{
    int lin = blockIdx.x;          // (b,h,i)
    int i = lin & 63, h = (lin >> 6) & 3, b = lin >> 8;
    __shared__ float sm[64][65];   // [l][j]
    __shared__ float red[4][64];
    float* base = g_s + ((size_t)(b*4+h))*262144 + i*64;
    for (int e = threadIdx.x; e < 4096; e += 256) {
        int l = e >> 6, j = e & 63;
        sm[l][j] = base[(size_t)l*4096 + j];
    }
    __syncthreads();
    int j = threadIdx.x & 63, g = threadIdx.x >> 6;
    int l0 = g * 16;
    float mx = -1e30f;
    #pragma unroll
    for (int l = 0; l < 16; l++) mx = fmaxf(mx, sm[l0+l][j]);
    red[g][j] = mx;
    __syncthreads();
    mx = fmaxf(fmaxf(red[0][j], red[1][j]), fmaxf(red[2][j], red[3][j]));
    __syncthreads();
    float ev[16];
    float sum = 0.f;
    #pragma unroll
    for (int l = 0; l < 16; l++) { float e = __expf(sm[l0+l][j] - mx); ev[l] = e; sum += e; }
    red[g][j] = sum;
    __syncthreads();
    sum = red[0][j] + red[1][j] + red[2][j] + red[3][j];
    float inv = 1.f / sum;
    #pragma unroll
    for (int l = 0; l < 16; l++) base[(size_t)(l0+l)*4096 + j] = ev[l] * inv;
}

// ---------------- combine: o[b,i,j,h,d] = sum_l a[b,h,l,i,j]*v1[b,i,l,h,d]*v2[b,l,j,h,d] ----------------
__global__ void __launch_bounds__(256) combine_kernel()
{
    int lin = blockIdx.x;          // (b,h,i)
    int i = lin & 63, h = (lin >> 6) & 3, b = lin >> 8;
    __shared__ float as_[64][65];      // [l][j]
    __shared__ float v1s[64][33];      // [l][d]
    __shared__ float v2s[2][64][33];   // double-buffered [j][d]
    const float* abase = g_s + ((size_t)(b*4+h))*262144 + i*64;
    for (int e = threadIdx.x; e < 4096; e += 256) {
        int l = e >> 6, j = e & 63;
        as_[l][j] = abase[(size_t)l*4096 + j];
    }
    for (int e = threadIdx.x; e < 2048; e += 256) {
        int l = e >> 5, d = e & 31;
        v1s[l][d] = g_v1[((size_t)((b*64+i)*64 + l))*128 + h*32 + d];
    }
    int j = threadIdx.x & 63, dg = threadIdx.x >> 6;  // dg in 0..3, 8 d's each
    float acc[8];
    #pragma unroll
    for (int k = 0; k < 8; k++) acc[k] = 0.f;

    for (int l = 0; l < 64; l++) {
        int buf = l & 1;
        for (int e = threadIdx.x; e < 2048; e += 256) {
            int jj = e >> 5, d = e & 31;
            v2s[buf][jj][d] = g_v2[((size_t)((b*64+l)*64 + jj))*128 + h*32 + d];
        }
        __syncthreads();
        float av = as_[l][j];
        const float* v1r = &v1s[l][dg*8];
        const float* v2r = &v2s[buf][j][dg*8];
        #pragma unroll
        for (int k = 0; k < 8; k++) acc[k] += av * v1r[k] * v2r[k];
    }
    float* op = g_o + ((size_t)((b*64+i)*64 + j))*128 + h*32 + dg*8;
    #pragma unroll
    for (int k = 0; k < 8; k++) op[k] = acc[k];
}

// ---------------- final head: out[b,n] = tok[b,n,n,:] @ Wout + bout ----------------
__global__ void out_kernel(const float* __restrict__ Wout, const float* __restrict__ bout,
                           float* __restrict__ out)
{
    int bn = blockIdx.x, d = threadIdx.x;
    int b = bn >> 6, n = bn & 63;
    float v = g_tok[((size_t)((b*64+n)*64 + n))*128 + d] * Wout[d];
    #pragma unroll
    for (int o = 16; o; o >>= 1) v += __shfl_xor_sync(0xffffffffu, v, o);
    __shared__ float ws[4];
    if ((d & 31) == 0) ws[d >> 5] = v;
    __syncthreads();
    if (d == 0) out[bn] = ws[0] + ws[1] + ws[2] + ws[3] + bout[0];
}

// ---------------- host orchestration ----------------
extern "C" void kernel_launch(void* const* d_in, const int* in_sizes, int n_in,
                              void* d_out, int out_size)
{
    const float* x    = (const float*)d_in[0];
    const float* ea   = (const float*)d_in[1];
    const int*   mask = (const int*)d_in[2];
    const float* nW   = (const float*)d_in[3];
    const float* nb   = (const float*)d_in[4];
    const float* eW   = (const float*)d_in[5];
    const float* eb   = (const float*)d_in[6];
    const float* noe  = (const float*)d_in[7];
    const float* Wq   = (const float*)d_in[8];
    const float* Wk   = (const float*)d_in[9];
    const float* Wv1  = (const float*)d_in[10];
    const float* Wv2  = (const float*)d_in[11];
    const float* Wo   = (const float*)d_in[12];
    const float* bo   = (const float*)d_in[13];
    const float* ln1g = (const float*)d_in[14];
    const float* ln1b = (const float*)d_in[15];
    const float* W1   = (const float*)d_in[16];
    const float* b1   = (const float*)d_in[17];
    const float* W2   = (const float*)d_in[18];
    const float* b2   = (const float*)d_in[19];
    const float* ln2g = (const float*)d_in[20];
    const float* ln2b = (const float*)d_in[21];
    const float* Wout = (const float*)d_in[22];
    const float* bout = (const float*)d_in[23];
    float* out = (float*)d_out;

    float *tok, *q, *k, *v1, *v2, *o, *hid;
    cudaGetSymbolAddress((void**)&tok, g_tok);
    cudaGetSymbolAddress((void**)&q,   g_q);
    cudaGetSymbolAddress((void**)&k,   g_k);
    cudaGetSymbolAddress((void**)&v1,  g_v1);
    cudaGetSymbolAddress((void**)&v2,  g_v2);
    cudaGetSymbolAddress((void**)&o,   g_o);
    cudaGetSymbolAddress((void**)&hid, g_hid);

    embed_kernel<<<Mm, 128>>>(x, ea, mask, nW, nb, eW, eb, noe);

    for (int l = 0; l < Llay; l++) {
        Ptr8 p;
        p.w[0] = Wq  + (size_t)l*128*128;
        p.w[1] = Wk  + (size_t)l*128*128;
        p.w[2] = Wv1 + (size_t)l*128*128;
        p.w[3] = Wv2 + (size_t)l*128*128;
        p.c[0] = q; p.c[1] = k; p.c[2] = v1; p.c[3] = v2;
        sgemm4_kernel<<<dim3(1, Mm/128, 4), 256>>>(tok, p);

        scores_kernel <<<Bb*Hh*Nn, 256>>>();
        softmax_kernel<<<Bb*Hh*Nn, 256>>>();
        combine_kernel<<<Bb*Hh*Nn, 256>>>();

        // tok = LN(tok + o@Wo + bo)   (fused epilogue)
        sgemm_ln_kernel<<<dim3(1, Mm/128), 256>>>(o, Wo + (size_t)l*128*128, tok,
                                                  bo + l*128, ln1g + l*128, ln1b + l*128, 128);

        // ff
        sgemm_bias_relu_kernel<<<dim3(FFf/128, Mm/128), 256>>>(tok, W1 + (size_t)l*128*512,
                                                               hid, b1 + l*512, 512, 128);
        // tok = LN(tok + hid@W2 + b2) (fused epilogue)
        sgemm_ln_kernel<<<dim3(1, Mm/128), 256>>>(hid, W2 + (size_t)l*512*128, tok,
                                                  b2 + l*128, ln2g + l*128, ln2b + l*128, 512);
    }

    out_kernel<<<Bb*Nn, 128>>>(Wout, bout, out);
}

// round 4
// speedup vs baseline: 1.3267x; 1.2020x over previous
#include <cuda_runtime.h>
#include <math.h>
#include <stdint.h>

// Problem constants
#define Bb   8
#define Nn   64
#define Dd   128
#define Hh   4
#define DHh  32
#define Llay 3
#define FFf  512
#define Mm   (Bb*Nn*Nn)   // 32768 tokens

// ---------------- scratch (device globals; no runtime allocation) ----------------
__device__ float g_tok[Mm*Dd];            // 16 MB
__device__ float g_q  [Mm*Dd];
__device__ float g_k  [Mm*Dd];
__device__ float g_v1 [Mm*Dd];
__device__ float g_v2 [Mm*Dd];
__device__ float g_s  [Bb*Hh*Nn*Nn*Nn];   // [b,h,l,i,j]  33.5 MB
__device__ float g_o  [Mm*Dd];
__device__ float g_hid[Mm*FFf];           // 64 MB

// ---------------- helpers ----------------
__device__ __forceinline__ float tf32f(float x) {
    uint32_t u; asm("cvt.rna.tf32.f32 %0, %1;" : "=r"(u) : "f"(x));
    return __uint_as_float(u);
}
__device__ __forceinline__ void mma8(float* c, const uint32_t* a, uint32_t b0, uint32_t b1) {
    asm volatile("mma.sync.aligned.m16n8k8.row.col.f32.tf32.tf32.f32 "
                 "{%0,%1,%2,%3}, {%4,%5,%6,%7}, {%8,%9}, {%0,%1,%2,%3};"
                 : "+f"(c[0]), "+f"(c[1]), "+f"(c[2]), "+f"(c[3])
                 : "r"(a[0]), "r"(a[1]), "r"(a[2]), "r"(a[3]), "r"(b0), "r"(b1));
}

// ---------------- embedding ----------------
__global__ void embed_kernel(const float* __restrict__ x, const float* __restrict__ ea,
                             const int* __restrict__ mask,
                             const float* __restrict__ nW, const float* __restrict__ nb,
                             const float* __restrict__ eW, const float* __restrict__ eb,
                             const float* __restrict__ noe)
{
    int m = blockIdx.x;           // token index (b,i,j)
    int d = threadIdx.x;          // 0..127
    int b = m >> 12;
    int i = (m >> 6) & 63;
    int j = m & 63;
    __shared__ float in_s[16];
    if (i == j) {
        if (d < 16) in_s[d] = x[(b*64+i)*16 + d];
        __syncthreads();
        float acc = nb[d];
        #pragma unroll
        for (int k = 0; k < 16; k++) acc += in_s[k] * nW[k*128 + d];
        g_tok[(size_t)m*128 + d] = acc;
    } else if (mask[m] != 0) {
        if (d < 8) in_s[d] = ea[(size_t)m*8 + d];
        __syncthreads();
        float acc = eb[d];
        #pragma unroll
        for (int k = 0; k < 8; k++) acc += in_s[k] * eW[k*128 + d];
        g_tok[(size_t)m*128 + d] = acc;
    } else {
        g_tok[(size_t)m*128 + d] = noe[d];
    }
}

// ---------------- TF32 tensor-core GEMM: 128x128 tile, BK=16, double-buffered ----------------
// 256 threads = 8 warps in 2(m) x 4(n); warp tile 64x32 via 4x4 m16n8k8 fragments.
// EPI: 0 = plain store, 1 = bias+relu store, 2 = fused residual+bias+LayerNorm into C (Ndim=128,n0=0)
#define AS(buf,k,m_) small[(buf)*2112 + (k)*132 + (m_)]
#define BS(buf,k,n_) small[4224 + (buf)*2112 + (k)*132 + (n_)]

template<int EPI>
__device__ __forceinline__ void mma_core(const float* __restrict__ A,
                                         const float* __restrict__ W,
                                         float* __restrict__ C,
                                         const float* __restrict__ bias,
                                         const float* __restrict__ gamma,
                                         const float* __restrict__ beta,
                                         int Ndim, int Kdim, int m0, int n0)
{
    __shared__ float small[8448];   // As[2][16][132] ++ Bs[2][16][132]; reused for LN reduce

    const int t    = threadIdx.x;
    const int lane = t & 31;
    const int wid  = t >> 5;
    const int wm   = wid >> 2;          // 0..1
    const int wn   = wid & 3;           // 0..3
    const int g    = lane >> 2;         // 0..7
    const int tig  = lane & 3;          // 0..3

    const int arow = t >> 1,  acol = (t & 1) * 8;   // A: 128 rows x 16 k
    const int brow = t >> 5,  bcol = (t & 31) * 4;  // B: 16 k x 128 n (rows brow, brow+8)

    const float* Aptr = A + (size_t)(m0 + arow) * Kdim + acol;
    const float* Wptr = W + (size_t)brow * Ndim + n0 + bcol;
    const size_t WrowStep = (size_t)8 * Ndim;

    float c_[4][4][4];
    #pragma unroll
    for (int mi = 0; mi < 4; mi++)
        #pragma unroll
        for (int ni = 0; ni < 4; ni++)
            #pragma unroll
            for (int r = 0; r < 4; r++) c_[mi][ni][r] = 0.f;

    // prefetch block 0
    float4 a0 = *(const float4*)(Aptr);
    float4 a1 = *(const float4*)(Aptr + 4);
    float4 b0 = *(const float4*)(Wptr);
    float4 b1 = *(const float4*)(Wptr + WrowStep);
    {
        float av[8] = {a0.x,a0.y,a0.z,a0.w,a1.x,a1.y,a1.z,a1.w};
        #pragma unroll
        for (int c = 0; c < 8; c++) AS(0, acol+c, arow) = tf32f(av[c]);
        float bv0[4] = {b0.x,b0.y,b0.z,b0.w};
        float bv1[4] = {b1.x,b1.y,b1.z,b1.w};
        #pragma unroll
        for (int c = 0; c < 4; c++) { BS(0, brow, bcol+c) = tf32f(bv0[c]); BS(0, brow+8, bcol+c) = tf32f(bv1[c]); }
    }
    __syncthreads();

    const int nk = Kdim >> 4;
    for (int kb = 0; kb < nk; kb++) {
        const int cur = kb & 1;
        if (kb + 1 < nk) {
            const float* Ap = Aptr + (kb+1)*16;
            const float* Wp = Wptr + (size_t)(kb+1)*16*Ndim;
            a0 = *(const float4*)(Ap);
            a1 = *(const float4*)(Ap + 4);
            b0 = *(const float4*)(Wp);
            b1 = *(const float4*)(Wp + WrowStep);
        }
        #pragma unroll
        for (int k8 = 0; k8 < 16; k8 += 8) {
            uint32_t af[4][4];
            #pragma unroll
            for (int mi = 0; mi < 4; mi++) {
                int mm = wm*64 + mi*16 + g;
                af[mi][0] = __float_as_uint(AS(cur, k8+tig,   mm));
                af[mi][1] = __float_as_uint(AS(cur, k8+tig,   mm+8));
                af[mi][2] = __float_as_uint(AS(cur, k8+tig+4, mm));
                af[mi][3] = __float_as_uint(AS(cur, k8+tig+4, mm+8));
            }
            #pragma unroll
            for (int ni = 0; ni < 4; ni++) {
                int nn = wn*32 + ni*8 + g;
                uint32_t bf0 = __float_as_uint(BS(cur, k8+tig,   nn));
                uint32_t bf1 = __float_as_uint(BS(cur, k8+tig+4, nn));
                #pragma unroll
                for (int mi = 0; mi < 4; mi++) mma8(c_[mi][ni], af[mi], bf0, bf1);
            }
        }
        if (kb + 1 < nk) {
            const int nxt = cur ^ 1;
            float av[8] = {a0.x,a0.y,a0.z,a0.w,a1.x,a1.y,a1.z,a1.w};
            #pragma unroll
            for (int c = 0; c < 8; c++) AS(nxt, acol+c, arow) = tf32f(av[c]);
            float bv0[4] = {b0.x,b0.y,b0.z,b0.w};
            float bv1[4] = {b1.x,b1.y,b1.z,b1.w};
            #pragma unroll
            for (int c = 0; c < 4; c++) { BS(nxt, brow, bcol+c) = tf32f(bv0[c]); BS(nxt, brow+8, bcol+c) = tf32f(bv1[c]); }
            __syncthreads();
        }
    }

    if (EPI == 2) {
        // fused residual + bias + LayerNorm; Ndim==128, n0==0, C == tok (also residual)
        __syncthreads();                        // As/Bs dead; reuse for reductions
        float* ps  = small;                     // [128][16] sum partials
        float* ps2 = small + 2048;              // [128][16] sumsq partials
        float* pmv = small + 4096;              // mean per row
        float* prv = small + 4224;              // rstd per row

        float biasv[4][2], gm[4][2], bt[4][2];
        #pragma unroll
        for (int ni = 0; ni < 4; ni++) {
            int col = wn*32 + ni*8 + 2*tig;
            float2 v;
            v = *(const float2*)(bias  + col); biasv[ni][0] = v.x; biasv[ni][1] = v.y;
            v = *(const float2*)(gamma + col); gm[ni][0] = v.x; gm[ni][1] = v.y;
            v = *(const float2*)(beta  + col); bt[ni][0] = v.x; bt[ni][1] = v.y;
        }
        #pragma unroll
        for (int mi = 0; mi < 4; mi++) {
            #pragma unroll
            for (int hh = 0; hh < 2; hh++) {
                int lrow = wm*64 + mi*16 + g + hh*8;
                size_t m = (size_t)(m0 + lrow);
                float s = 0.f, s2 = 0.f;
                #pragma unroll
                for (int ni = 0; ni < 4; ni++) {
                    int col = wn*32 + ni*8 + 2*tig;
                    float2 res = *(const float2*)(C + m*128 + col);
                    float v0 = c_[mi][ni][hh*2+0] + res.x + biasv[ni][0];
                    float v1 = c_[mi][ni][hh*2+1] + res.y + biasv[ni][1];
                    c_[mi][ni][hh*2+0] = v0;
                    c_[mi][ni][hh*2+1] = v1;
                    s += v0 + v1; s2 += v0*v0 + v1*v1;
                }
                ps [lrow*16 + wn*4 + tig] = s;
                ps2[lrow*16 + wn*4 + tig] = s2;
            }
        }
        __syncthreads();
        if (t < 128) {
            float s = 0.f, s2 = 0.f;
            #pragma unroll
            for (int i = 0; i < 16; i++) { s += ps[t*16+i]; s2 += ps2[t*16+i]; }
            float mean = s * (1.f/128.f);
            float var  = s2 * (1.f/128.f) - mean*mean;
            pmv[t] = mean;
            prv[t] = rsqrtf(var + 1e-5f);
        }
        __syncthreads();
        #pragma unroll
        for (int mi = 0; mi < 4; mi++) {
            #pragma unroll
            for (int hh = 0; hh < 2; hh++) {
                int lrow = wm*64 + mi*16 + g + hh*8;
                size_t m = (size_t)(m0 + lrow);
                float mean = pmv[lrow], r = prv[lrow];
                #pragma unroll
                for (int ni = 0; ni < 4; ni++) {
                    int col = wn*32 + ni*8 + 2*tig;
                    float2 o;
                    o.x = (c_[mi][ni][hh*2+0] - mean) * r * gm[ni][0] + bt[ni][0];
                    o.y = (c_[mi][ni][hh*2+1] - mean) * r * gm[ni][1] + bt[ni][1];
                    *(float2*)(C + m*128 + col) = o;
                }
            }
        }
    } else {
        #pragma unroll
        for (int mi = 0; mi < 4; mi++) {
            #pragma unroll
            for (int hh = 0; hh < 2; hh++) {
                size_t m = (size_t)(m0 + wm*64 + mi*16 + g + hh*8);
                #pragma unroll
                for (int ni = 0; ni < 4; ni++) {
                    int col = n0 + wn*32 + ni*8 + 2*tig;
                    float v0 = c_[mi][ni][hh*2+0];
                    float v1 = c_[mi][ni][hh*2+1];
                    if (EPI == 1) {
                        v0 = fmaxf(v0 + bias[col],   0.f);
                        v1 = fmaxf(v1 + bias[col+1], 0.f);
                    }
                    float2 o; o.x = v0; o.y = v1;
                    *(float2*)(C + m * Ndim + col) = o;
                }
            }
        }
    }
}

struct Ptr8 { const float* w[4]; float* c[4]; };

__global__ void __launch_bounds__(256) sgemm4_kernel(const float* A, Ptr8 p)
{
    mma_core<0>(A, p.w[blockIdx.z], p.c[blockIdx.z], nullptr, nullptr, nullptr,
                128, 128, blockIdx.y * 128, 0);
}
__global__ void __launch_bounds__(256) sgemm_bias_relu_kernel(const float* A, const float* W,
                                                              float* C, const float* bias,
                                                              int Ndim, int Kdim)
{
    mma_core<1>(A, W, C, bias, nullptr, nullptr, Ndim, Kdim,
                blockIdx.y * 128, blockIdx.x * 128);
}
__global__ void __launch_bounds__(256) sgemm_ln_kernel(const float* A, const float* W,
                                                       float* TOK, const float* bias,
                                                       const float* gamma, const float* beta,
                                                       int Kdim)
{
    mma_core<2>(A, W, TOK, bias, gamma, beta, 128, Kdim, blockIdx.y * 128, 0);
}

// ---------------- attention scores: s[b,h,l,i,j] = Q_l @ K_l^T / sqrt(DH) ----------------
__global__ void __launch_bounds__(256) scores_kernel()
{
    int lin = blockIdx.x;          // (b,h,l)
    int l = lin & 63, h = (lin >> 6) & 3, b = lin >> 8;
    __shared__ float Qs[32][68];   // [d][i]
    __shared__ float Ks[32][68];   // [d][j]
    for (int e = threadIdx.x; e < 2048; e += 256) {
        int i = e >> 5, d = e & 31;
        Qs[d][i] = g_q[((size_t)((b*64+i)*64 + l))*128 + h*32 + d];
        Ks[d][i] = g_k[((size_t)((b*64+l)*64 + i))*128 + h*32 + d];
    }
    __syncthreads();
    int ti = threadIdx.x >> 4, tj = threadIdx.x & 15;
    int i0 = ti*4, j0 = tj*4;
    float acc[4][4];
    #pragma unroll
    for (int a = 0; a < 4; a++)
        #pragma unroll
        for (int c = 0; c < 4; c++) acc[a][c] = 0.f;
    #pragma unroll
    for (int d = 0; d < 32; d++) {
        float4 ra = *(const float4*)&Qs[d][i0];
        float4 rb = *(const float4*)&Ks[d][j0];
        float A[4] = {ra.x, ra.y, ra.z, ra.w};
        float Bv[4] = {rb.x, rb.y, rb.z, rb.w};
        #pragma unroll
        for (int ii = 0; ii < 4; ii++)
            #pragma unroll
            for (int jj = 0; jj < 4; jj++)
                acc[ii][jj] += A[ii] * Bv[jj];
    }
    const float isc = 0.17677669529663687f;   // 1/sqrt(32)
    float* sp = g_s + ((size_t)((b*4+h)*64 + l)) * 4096;
    #pragma unroll
    for (int ii = 0; ii < 4; ii++) {
        float4 v = make_float4(acc[ii][0]*isc, acc[ii][1]*isc, acc[ii][2]*isc, acc[ii][3]*isc);
        *(float4*)(sp + (i0+ii)*64 + j0) = v;
    }
}

// ---------------- softmax over l (axis 3): parallel over all 256 threads ----------------
__global__ void __launch_bounds__(256) softmax_kernel()
{
    int lin = blockIdx.x;          // (b,h,i)
    int i = lin & 63, h = (lin >> 6) & 3, b = lin >> 8;
    __shared__ float sm[64][65];   // [l][j]
    __shared__ float red[4][64];
    float* base = g_s + ((size_t)(b*4+h))*262144 + i*64;
    for (int e = threadIdx.x; e < 4096; e += 256) {
        int l = e >> 6, j = e & 63;
        sm[l][j] = base[(size_t)l*4096 + j];
    }
    __syncthreads();
    int j = threadIdx.x & 63, g = threadIdx.x >> 6;
    int l0 = g * 16;
    float mx = -1e30f;
    #pragma unroll
    for (int l = 0; l < 16; l++) mx = fmaxf(mx, sm[l0+l][j]);
    red[g][j] = mx;
    __syncthreads();
    mx = fmaxf(fmaxf(red[0][j], red[1][j]), fmaxf(red[2][j], red[3][j]));
    __syncthreads();
    float ev[16];
    float sum = 0.f;
    #pragma unroll
    for (int l = 0; l < 16; l++) { float e = __expf(sm[l0+l][j] - mx); ev[l] = e; sum += e; }
    red[g][j] = sum;
    __syncthreads();
    sum = red[0][j] + red[1][j] + red[2][j] + red[3][j];
    float inv = 1.f / sum;
    #pragma unroll
    for (int l = 0; l < 16; l++) base[(size_t)(l0+l)*4096 + j] = ev[l] * inv;
}

// ---------------- combine: o[b,i,j,h,d] = sum_l a[b,h,l,i,j]*v1[b,i,l,h,d]*v2[b,l,j,h,d] ----------------
__global__ void __launch_bounds__(256) combine_kernel()
{
    int lin = blockIdx.x;          // (b,h,i)
    int i = lin & 63, h = (lin >> 6) & 3, b = lin >> 8;
    __shared__ float as_[64][65];      // [l][j]
    __shared__ float v1s[64][33];      // [l][d]
    __shared__ float v2s[2][64][33];   // double-buffered [j][d]
    const float* abase = g_s + ((size_t)(b*4+h))*262144 + i*64;
    for (int e = threadIdx.x; e < 4096; e += 256) {
        int l = e >> 6, j = e & 63;
        as_[l][j] = abase[(size_t)l*4096 + j];
    }
    for (int e = threadIdx.x; e < 2048; e += 256) {
        int l = e >> 5, d = e & 31;
        v1s[l][d] = g_v1[((size_t)((b*64+i)*64 + l))*128 + h*32 + d];
    }
    int j = threadIdx.x & 63, dg = threadIdx.x >> 6;  // dg in 0..3, 8 d's each
    float acc[8];
    #pragma unroll
    for (int k = 0; k < 8; k++) acc[k] = 0.f;

    for (int l = 0; l < 64; l++) {
        int buf = l & 1;
        for (int e = threadIdx.x; e < 2048; e += 256) {
            int jj = e >> 5, d = e & 31;
            v2s[buf][jj][d] = g_v2[((size_t)((b*64+l)*64 + jj))*128 + h*32 + d];
        }
        __syncthreads();
        float av = as_[l][j];
        const float* v1r = &v1s[l][dg*8];
        const float* v2r = &v2s[buf][j][dg*8];
        #pragma unroll
        for (int k = 0; k < 8; k++) acc[k] += av * v1r[k] * v2r[k];
    }
    float* op = g_o + ((size_t)((b*64+i)*64 + j))*128 + h*32 + dg*8;
    #pragma unroll
    for (int k = 0; k < 8; k++) op[k] = acc[k];
}

// ---------------- final head: out[b,n] = tok[b,n,n,:] @ Wout + bout ----------------
__global__ void out_kernel(const float* __restrict__ Wout, const float* __restrict__ bout,
                           float* __restrict__ out)
{
    int bn = blockIdx.x, d = threadIdx.x;
    int b = bn >> 6, n = bn & 63;
    float v = g_tok[((size_t)((b*64+n)*64 + n))*128 + d] * Wout[d];
    #pragma unroll
    for (int o = 16; o; o >>= 1) v += __shfl_xor_sync(0xffffffffu, v, o);
    __shared__ float ws[4];
    if ((d & 31) == 0) ws[d >> 5] = v;
    __syncthreads();
    if (d == 0) out[bn] = ws[0] + ws[1] + ws[2] + ws[3] + bout[0];
}

// ---------------- host orchestration ----------------
extern "C" void kernel_launch(void* const* d_in, const int* in_sizes, int n_in,
                              void* d_out, int out_size)
{
    const float* x    = (const float*)d_in[0];
    const float* ea   = (const float*)d_in[1];
    const int*   mask = (const int*)d_in[2];
    const float* nW   = (const float*)d_in[3];
    const float* nb   = (const float*)d_in[4];
    const float* eW   = (const float*)d_in[5];
    const float* eb   = (const float*)d_in[6];
    const float* noe  = (const float*)d_in[7];
    const float* Wq   = (const float*)d_in[8];
    const float* Wk   = (const float*)d_in[9];
    const float* Wv1  = (const float*)d_in[10];
    const float* Wv2  = (const float*)d_in[11];
    const float* Wo   = (const float*)d_in[12];
    const float* bo   = (const float*)d_in[13];
    const float* ln1g = (const float*)d_in[14];
    const float* ln1b = (const float*)d_in[15];
    const float* W1   = (const float*)d_in[16];
    const float* b1   = (const float*)d_in[17];
    const float* W2   = (const float*)d_in[18];
    const float* b2   = (const float*)d_in[19];
    const float* ln2g = (const float*)d_in[20];
    const float* ln2b = (const float*)d_in[21];
    const float* Wout = (const float*)d_in[22];
    const float* bout = (const float*)d_in[23];
    float* out = (float*)d_out;

    float *tok, *q, *k, *v1, *v2, *o, *hid;
    cudaGetSymbolAddress((void**)&tok, g_tok);
    cudaGetSymbolAddress((void**)&q,   g_q);
    cudaGetSymbolAddress((void**)&k,   g_k);
    cudaGetSymbolAddress((void**)&v1,  g_v1);
    cudaGetSymbolAddress((void**)&v2,  g_v2);
    cudaGetSymbolAddress((void**)&o,   g_o);
    cudaGetSymbolAddress((void**)&hid, g_hid);

    embed_kernel<<<Mm, 128>>>(x, ea, mask, nW, nb, eW, eb, noe);

    for (int l = 0; l < Llay; l++) {
        Ptr8 p;
        p.w[0] = Wq  + (size_t)l*128*128;
        p.w[1] = Wk  + (size_t)l*128*128;
        p.w[2] = Wv1 + (size_t)l*128*128;
        p.w[3] = Wv2 + (size_t)l*128*128;
        p.c[0] = q; p.c[1] = k; p.c[2] = v1; p.c[3] = v2;
        sgemm4_kernel<<<dim3(1, Mm/128, 4), 256>>>(tok, p);

        scores_kernel <<<Bb*Hh*Nn, 256>>>();
        softmax_kernel<<<Bb*Hh*Nn, 256>>>();
        combine_kernel<<<Bb*Hh*Nn, 256>>>();

        // tok = LN(tok + o@Wo + bo)   (fused epilogue)
        sgemm_ln_kernel<<<dim3(1, Mm/128), 256>>>(o, Wo + (size_t)l*128*128, tok,
                                                  bo + l*128, ln1g + l*128, ln1b + l*128, 128);

        // ff
        sgemm_bias_relu_kernel<<<dim3(FFf/128, Mm/128), 256>>>(tok, W1 + (size_t)l*128*512,
                                                               hid, b1 + l*512, 512, 128);
        // tok = LN(tok + hid@W2 + b2) (fused epilogue)
        sgemm_ln_kernel<<<dim3(1, Mm/128), 256>>>(hid, W2 + (size_t)l*512*128, tok,
                                                  b2 + l*128, ln2g + l*128, ln2b + l*128, 512);
    }

    out_kernel<<<Bb*Nn, 128>>>(Wout, bout, out);
}

// round 5
// speedup vs baseline: 2.1905x; 1.6510x over previous
#include <cuda_runtime.h>
#include <math.h>
#include <stdint.h>

// Problem constants
#define Bb   8
#define Nn   64
#define Dd   128
#define Hh   4
#define DHh  32
#define Llay 3
#define FFf  512
#define Mm   (Bb*Nn*Nn)   // 32768 tokens

// ---------------- scratch (device globals; no runtime allocation) ----------------
__device__ float g_tok[Mm*Dd];            // 16 MB
__device__ float g_q  [Mm*Dd];
__device__ float g_k  [Mm*Dd];
__device__ float g_v1 [Mm*Dd];
__device__ float g_v2 [Mm*Dd];
__device__ float g_s  [Bb*Hh*Nn*Nn*Nn];   // [b,h,l,i,j]  33.5 MB
__device__ float g_o  [Mm*Dd];
__device__ float g_hid[Mm*FFf];           // 64 MB

// ---------------- helpers ----------------
__device__ __forceinline__ void mma8(float* c, const uint32_t* a, uint32_t b0, uint32_t b1) {
    asm volatile("mma.sync.aligned.m16n8k8.row.col.f32.tf32.tf32.f32 "
                 "{%0,%1,%2,%3}, {%4,%5,%6,%7}, {%8,%9}, {%0,%1,%2,%3};"
                 : "+f"(c[0]), "+f"(c[1]), "+f"(c[2]), "+f"(c[3])
                 : "r"(a[0]), "r"(a[1]), "r"(a[2]), "r"(a[3]), "r"(b0), "r"(b1));
}
__device__ __forceinline__ void cp16(void* dst_smem, const void* src) {
    uint32_t d = (uint32_t)__cvta_generic_to_shared(dst_smem);
    asm volatile("cp.async.cg.shared.global [%0], [%1], 16;" :: "r"(d), "l"(src) : "memory");
}
__device__ __forceinline__ void cp4(void* dst_smem, const void* src) {
    uint32_t d = (uint32_t)__cvta_generic_to_shared(dst_smem);
    asm volatile("cp.async.ca.shared.global [%0], [%1], 4;" :: "r"(d), "l"(src) : "memory");
}
__device__ __forceinline__ void cp_commit() {
    asm volatile("cp.async.commit_group;" ::: "memory");
}
template<int N>
__device__ __forceinline__ void cp_wait() {
    asm volatile("cp.async.wait_group %0;" :: "n"(N) : "memory");
}

// ---------------- embedding ----------------
__global__ void embed_kernel(const float* __restrict__ x, const float* __restrict__ ea,
                             const int* __restrict__ mask,
                             const float* __restrict__ nW, const float* __restrict__ nb,
                             const float* __restrict__ eW, const float* __restrict__ eb,
                             const float* __restrict__ noe)
{
    int m = blockIdx.x;           // token index (b,i,j)
    int d = threadIdx.x;          // 0..127
    int b = m >> 12;
    int i = (m >> 6) & 63;
    int j = m & 63;
    __shared__ float in_s[16];
    if (i == j) {
        if (d < 16) in_s[d] = x[(b*64+i)*16 + d];
        __syncthreads();
        float acc = nb[d];
        #pragma unroll
        for (int k = 0; k < 16; k++) acc += in_s[k] * nW[k*128 + d];
        g_tok[(size_t)m*128 + d] = acc;
    } else if (mask[m] != 0) {
        if (d < 8) in_s[d] = ea[(size_t)m*8 + d];
        __syncthreads();
        float acc = eb[d];
        #pragma unroll
        for (int k = 0; k < 8; k++) acc += in_s[k] * eW[k*128 + d];
        g_tok[(size_t)m*128 + d] = acc;
    } else {
        g_tok[(size_t)m*128 + d] = noe[d];
    }
}

// ---------------- TF32 tensor-core GEMM: 128x128 CTA tile, BK=16, cp.async double-buffer ----------------
// 128 threads = 4 warps in 2(m) x 2(n); warp tile 64x64 via 4x8 m16n8k8 fragments.
// EPI: 0 = plain store, 1 = bias+relu store, 2 = fused residual+bias+LayerNorm into C (Ndim=128,n0=0)
template<int EPI>
__device__ __forceinline__ void mma_core(const float* __restrict__ A,
                                         const float* __restrict__ W,
                                         float* __restrict__ C,
                                         const float* __restrict__ bias,
                                         const float* __restrict__ gamma,
                                         const float* __restrict__ beta,
                                         int Ndim, int Kdim, int m0, int n0)
{
    __shared__ float As[2][128][20];   // [buf][m][k(16)+pad4] — frag loads conflict-free
    __shared__ float Bs[2][16][136];   // [buf][k][n(128)+pad8]
    __shared__ float ps[128][2], ps2[128][2], pmv[128], prv[128];

    const int t    = threadIdx.x;
    const int lane = t & 31;
    const int w    = t >> 5;
    const int wm   = w >> 1;            // 0..1
    const int wn   = w & 1;             // 0..1
    const int g    = lane >> 2;         // 0..7
    const int tig  = lane & 3;          // 0..3

    float c_[4][8][4];
    #pragma unroll
    for (int mi = 0; mi < 4; mi++)
        #pragma unroll
        for (int ni = 0; ni < 8; ni++)
            #pragma unroll
            for (int r = 0; r < 4; r++) c_[mi][ni][r] = 0.f;

    auto issue = [&](int kb, int buf) {
        #pragma unroll
        for (int q = 0; q < 4; q++) {          // A tile: 128 rows x 16k = 512 float4
            int idx = q*128 + t;
            int m = idx >> 2, f4 = idx & 3;
            cp16(&As[buf][m][f4*4], A + (size_t)(m0+m)*Kdim + kb*16 + f4*4);
        }
        #pragma unroll
        for (int q = 0; q < 4; q++) {          // B tile: 16k x 128n = 512 float4
            int idx = q*128 + t;
            int k = idx >> 5, n4 = idx & 31;
            cp16(&Bs[buf][k][n4*4], W + (size_t)(kb*16+k)*Ndim + n0 + n4*4);
        }
        cp_commit();
    };

    issue(0, 0);
    const int nk = Kdim >> 4;
    for (int kb = 0; kb < nk; kb++) {
        const int cur = kb & 1;
        cp_wait<0>();
        __syncthreads();
        if (kb + 1 < nk) issue(kb+1, cur ^ 1);

        #pragma unroll
        for (int k8 = 0; k8 < 16; k8 += 8) {
            uint32_t af[4][4];
            #pragma unroll
            for (int mi = 0; mi < 4; mi++) {
                int mm = wm*64 + mi*16 + g;
                af[mi][0] = __float_as_uint(As[cur][mm  ][k8+tig]);
                af[mi][1] = __float_as_uint(As[cur][mm+8][k8+tig]);
                af[mi][2] = __float_as_uint(As[cur][mm  ][k8+tig+4]);
                af[mi][3] = __float_as_uint(As[cur][mm+8][k8+tig+4]);
            }
            uint32_t bf[8][2];
            #pragma unroll
            for (int ni = 0; ni < 8; ni++) {
                int nn = wn*64 + ni*8 + g;
                bf[ni][0] = __float_as_uint(Bs[cur][k8+tig  ][nn]);
                bf[ni][1] = __float_as_uint(Bs[cur][k8+tig+4][nn]);
            }
            #pragma unroll
            for (int mi = 0; mi < 4; mi++)
                #pragma unroll
                for (int ni = 0; ni < 8; ni++)
                    mma8(c_[mi][ni], af[mi], bf[ni][0], bf[ni][1]);
        }
    }

    if (EPI == 2) {
        // fused residual + bias + LayerNorm; Ndim==128, n0==0, C == tok (also residual)
        float bi[8][2], gm[8][2], bt[8][2];
        #pragma unroll
        for (int ni = 0; ni < 8; ni++) {
            int col = wn*64 + ni*8 + 2*tig;
            float2 v;
            v = *(const float2*)(bias  + col); bi[ni][0] = v.x; bi[ni][1] = v.y;
            v = *(const float2*)(gamma + col); gm[ni][0] = v.x; gm[ni][1] = v.y;
            v = *(const float2*)(beta  + col); bt[ni][0] = v.x; bt[ni][1] = v.y;
        }
        #pragma unroll
        for (int mi = 0; mi < 4; mi++) {
            #pragma unroll
            for (int hh = 0; hh < 2; hh++) {
                int lrow = wm*64 + mi*16 + g + hh*8;
                size_t m = (size_t)(m0 + lrow);
                float s = 0.f, s2 = 0.f;
                #pragma unroll
                for (int ni = 0; ni < 8; ni++) {
                    int col = wn*64 + ni*8 + 2*tig;
                    float2 res = *(const float2*)(C + m*128 + col);
                    float v0 = c_[mi][ni][hh*2+0] + res.x + bi[ni][0];
                    float v1 = c_[mi][ni][hh*2+1] + res.y + bi[ni][1];
                    c_[mi][ni][hh*2+0] = v0;
                    c_[mi][ni][hh*2+1] = v1;
                    s += v0 + v1; s2 += v0*v0 + v1*v1;
                }
                // quad reduce over tig (lanes g*4+tig)
                s  += __shfl_xor_sync(0xffffffffu, s,  1);
                s  += __shfl_xor_sync(0xffffffffu, s,  2);
                s2 += __shfl_xor_sync(0xffffffffu, s2, 1);
                s2 += __shfl_xor_sync(0xffffffffu, s2, 2);
                if (tig == 0) { ps[lrow][wn] = s; ps2[lrow][wn] = s2; }
            }
        }
        __syncthreads();
        if (t < 128) {
            float s = ps[t][0] + ps[t][1];
            float s2 = ps2[t][0] + ps2[t][1];
            float mean = s * (1.f/128.f);
            float var  = s2 * (1.f/128.f) - mean*mean;
            pmv[t] = mean;
            prv[t] = rsqrtf(var + 1e-5f);
        }
        __syncthreads();
        #pragma unroll
        for (int mi = 0; mi < 4; mi++) {
            #pragma unroll
            for (int hh = 0; hh < 2; hh++) {
                int lrow = wm*64 + mi*16 + g + hh*8;
                size_t m = (size_t)(m0 + lrow);
                float mean = pmv[lrow], r = prv[lrow];
                #pragma unroll
                for (int ni = 0; ni < 8; ni++) {
                    int col = wn*64 + ni*8 + 2*tig;
                    float2 o;
                    o.x = (c_[mi][ni][hh*2+0] - mean) * r * gm[ni][0] + bt[ni][0];
                    o.y = (c_[mi][ni][hh*2+1] - mean) * r * gm[ni][1] + bt[ni][1];
                    *(float2*)(C + m*128 + col) = o;
                }
            }
        }
    } else {
        #pragma unroll
        for (int mi = 0; mi < 4; mi++) {
            #pragma unroll
            for (int hh = 0; hh < 2; hh++) {
                size_t m = (size_t)(m0 + wm*64 + mi*16 + g + hh*8);
                #pragma unroll
                for (int ni = 0; ni < 8; ni++) {
                    int col = n0 + wn*64 + ni*8 + 2*tig;
                    float v0 = c_[mi][ni][hh*2+0];
                    float v1 = c_[mi][ni][hh*2+1];
                    if (EPI == 1) {
                        v0 = fmaxf(v0 + bias[col],   0.f);
                        v1 = fmaxf(v1 + bias[col+1], 0.f);
                    }
                    float2 o; o.x = v0; o.y = v1;
                    *(float2*)(C + m * Ndim + col) = o;
                }
            }
        }
    }
}

struct Ptr8 { const float* w[4]; float* c[4]; };

__global__ void __launch_bounds__(128) sgemm4_kernel(const float* A, Ptr8 p)
{
    mma_core<0>(A, p.w[blockIdx.z], p.c[blockIdx.z], nullptr, nullptr, nullptr,
                128, 128, blockIdx.y * 128, 0);
}
__global__ void __launch_bounds__(128) sgemm_bias_relu_kernel(const float* A, const float* W,
                                                              float* C, const float* bias,
                                                              int Ndim, int Kdim)
{
    mma_core<1>(A, W, C, bias, nullptr, nullptr, Ndim, Kdim,
                blockIdx.y * 128, blockIdx.x * 128);
}
__global__ void __launch_bounds__(128) sgemm_ln_kernel(const float* A, const float* W,
                                                       float* TOK, const float* bias,
                                                       const float* gamma, const float* beta,
                                                       int Kdim)
{
    mma_core<2>(A, W, TOK, bias, gamma, beta, 128, Kdim, blockIdx.y * 128, 0);
}

// ---------------- attention scores: s[b,h,l,i,j] = Q_l @ K_l^T / sqrt(DH) ----------------
__global__ void __launch_bounds__(256) scores_kernel()
{
    int lin = blockIdx.x;          // (b,h,l)
    int l = lin & 63, h = (lin >> 6) & 3, b = lin >> 8;
    __shared__ float Qs[32][68];   // [d][i]
    __shared__ float Ks[32][68];   // [d][j]
    for (int e = threadIdx.x; e < 2048; e += 256) {
        int i = e >> 5, d = e & 31;
        Qs[d][i] = g_q[((size_t)((b*64+i)*64 + l))*128 + h*32 + d];
        Ks[d][i] = g_k[((size_t)((b*64+l)*64 + i))*128 + h*32 + d];
    }
    __syncthreads();
    int ti = threadIdx.x >> 4, tj = threadIdx.x & 15;
    int i0 = ti*4, j0 = tj*4;
    float acc[4][4];
    #pragma unroll
    for (int a = 0; a < 4; a++)
        #pragma unroll
        for (int c = 0; c < 4; c++) acc[a][c] = 0.f;
    #pragma unroll
    for (int d = 0; d < 32; d++) {
        float4 ra = *(const float4*)&Qs[d][i0];
        float4 rb = *(const float4*)&Ks[d][j0];
        float A[4] = {ra.x, ra.y, ra.z, ra.w};
        float Bv[4] = {rb.x, rb.y, rb.z, rb.w};
        #pragma unroll
        for (int ii = 0; ii < 4; ii++)
            #pragma unroll
            for (int jj = 0; jj < 4; jj++)
                acc[ii][jj] += A[ii] * Bv[jj];
    }
    const float isc = 0.17677669529663687f;   // 1/sqrt(32)
    float* sp = g_s + ((size_t)((b*4+h)*64 + l)) * 4096;
    #pragma unroll
    for (int ii = 0; ii < 4; ii++) {
        float4 v = make_float4(acc[ii][0]*isc, acc[ii][1]*isc, acc[ii][2]*isc, acc[ii][3]*isc);
        *(float4*)(sp + (i0+ii)*64 + j0) = v;
    }
}

// ---------------- softmax over l (axis 3): parallel over all 256 threads ----------------
__global__ void __launch_bounds__(256) softmax_kernel()
{
    int lin = blockIdx.x;          // (b,h,i)
    int i = lin & 63, h = (lin >> 6) & 3, b = lin >> 8;
    __shared__ float sm[64][65];   // [l][j]
    __shared__ float red[4][64];
    float* base = g_s + ((size_t)(b*4+h))*262144 + i*64;
    for (int e = threadIdx.x; e < 4096; e += 256) {
        int l = e >> 6, j = e & 63;
        sm[l][j] = base[(size_t)l*4096 + j];
    }
    __syncthreads();
    int j = threadIdx.x & 63, g = threadIdx.x >> 6;
    int l0 = g * 16;
    float mx = -1e30f;
    #pragma unroll
    for (int l = 0; l < 16; l++) mx = fmaxf(mx, sm[l0+l][j]);
    red[g][j] = mx;
    __syncthreads();
    mx = fmaxf(fmaxf(red[0][j], red[1][j]), fmaxf(red[2][j], red[3][j]));
    __syncthreads();
    float ev[16];
    float sum = 0.f;
    #pragma unroll
    for (int l = 0; l < 16; l++) { float e = __expf(sm[l0+l][j] - mx); ev[l] = e; sum += e; }
    red[g][j] = sum;
    __syncthreads();
    sum = red[0][j] + red[1][j] + red[2][j] + red[3][j];
    float inv = 1.f / sum;
    #pragma unroll
    for (int l = 0; l < 16; l++) base[(size_t)(l0+l)*4096 + j] = ev[l] * inv;
}

// ---------------- combine: o[b,i,j,h,d] = sum_l a[b,h,l,i,j]*v1[b,i,l,h,d]*v2[b,l,j,h,d] ----------------
// i-tiled by 4; v2 slice triple-buffered via cp.async ring.
// dyn smem layout: a4[4][64][64] | v1s[4][64][32] | v2s[3][64][33]
#define CMB_SMEM ((16384 + 8192 + 3*2112) * 4)
__global__ void __launch_bounds__(512) combine_kernel()
{
    extern __shared__ float smc[];
    float* a4  = smc;            // [ii*4096 + l*64 + j]
    float* v1s = smc + 16384;    // [ii*2048 + l*32 + d]
    float* v2s = smc + 24576;    // [st*2112 + j*33 + d]

    int lin = blockIdx.x;        // (b,h,i4)
    int i4 = lin & 15, h = (lin >> 4) & 3, b = lin >> 6;
    int t = threadIdx.x;
    int j = t & 63, dg = t >> 6; // dg 0..7, 4 d's each

    const float* abase = g_s + ((size_t)(b*4+h))*262144;
    for (int e = t; e < 16384; e += 512) {
        int ii = e >> 12, l = (e >> 6) & 63, jj = e & 63;
        a4[ii*4096 + l*64 + jj] = abase[(size_t)l*4096 + (i4*4+ii)*64 + jj];
    }
    for (int e = t; e < 8192; e += 512) {
        int ii = e >> 11, l = (e >> 5) & 63, d = e & 31;
        v1s[ii*2048 + l*32 + d] = g_v1[((size_t)((b*64+i4*4+ii)*64 + l))*128 + h*32 + d];
    }

    auto issue_v2 = [&](int l, int st) {
        #pragma unroll
        for (int q = 0; q < 4; q++) {
            int e = q*512 + t;            // 2048 floats
            int jj = e >> 5, d = e & 31;
            cp4(&v2s[st*2112 + jj*33 + d],
                g_v2 + ((size_t)((b*64+l)*64 + jj))*128 + h*32 + d);
        }
        cp_commit();
    };

    float acc[4][4];
    #pragma unroll
    for (int ii = 0; ii < 4; ii++)
        #pragma unroll
        for (int k = 0; k < 4; k++) acc[ii][k] = 0.f;

    issue_v2(0, 0);
    issue_v2(1, 1);
    for (int l = 0; l < 64; l++) {
        if (l < 62) cp_wait<1>(); else cp_wait<0>();
        __syncthreads();
        if (l + 2 < 64) issue_v2(l+2, (l+2) % 3);
        int ls = (l % 3) * 2112;
        float v2r[4];
        #pragma unroll
        for (int k = 0; k < 4; k++) v2r[k] = v2s[ls + j*33 + dg*4 + k];
        #pragma unroll
        for (int ii = 0; ii < 4; ii++) {
            float av = a4[ii*4096 + l*64 + j];
            const float* v1p = &v1s[ii*2048 + l*32 + dg*4];
            #pragma unroll
            for (int k = 0; k < 4; k++) acc[ii][k] += av * v1p[k] * v2r[k];
        }
    }
    #pragma unroll
    for (int ii = 0; ii < 4; ii++) {
        int i = i4*4 + ii;
        float4 v = make_float4(acc[ii][0], acc[ii][1], acc[ii][2], acc[ii][3]);
        *(float4*)(g_o + ((size_t)((b*64+i)*64 + j))*128 + h*32 + dg*4) = v;
    }
}

// ---------------- final head: out[b,n] = tok[b,n,n,:] @ Wout + bout ----------------
__global__ void out_kernel(const float* __restrict__ Wout, const float* __restrict__ bout,
                           float* __restrict__ out)
{
    int bn = blockIdx.x, d = threadIdx.x;
    int b = bn >> 6, n = bn & 63;
    float v = g_tok[((size_t)((b*64+n)*64 + n))*128 + d] * Wout[d];
    #pragma unroll
    for (int o = 16; o; o >>= 1) v += __shfl_xor_sync(0xffffffffu, v, o);
    __shared__ float ws[4];
    if ((d & 31) == 0) ws[d >> 5] = v;
    __syncthreads();
    if (d == 0) out[bn] = ws[0] + ws[1] + ws[2] + ws[3] + bout[0];
}

// ---------------- host orchestration ----------------
extern "C" void kernel_launch(void* const* d_in, const int* in_sizes, int n_in,
                              void* d_out, int out_size)
{
    const float* x    = (const float*)d_in[0];
    const float* ea   = (const float*)d_in[1];
    const int*   mask = (const int*)d_in[2];
    const float* nW   = (const float*)d_in[3];
    const float* nb   = (const float*)d_in[4];
    const float* eW   = (const float*)d_in[5];
    const float* eb   = (const float*)d_in[6];
    const float* noe  = (const float*)d_in[7];
    const float* Wq   = (const float*)d_in[8];
    const float* Wk   = (const float*)d_in[9];
    const float* Wv1  = (const float*)d_in[10];
    const float* Wv2  = (const float*)d_in[11];
    const float* Wo   = (const float*)d_in[12];
    const float* bo   = (const float*)d_in[13];
    const float* ln1g = (const float*)d_in[14];
    const float* ln1b = (const float*)d_in[15];
    const float* W1   = (const float*)d_in[16];
    const float* b1   = (const float*)d_in[17];
    const float* W2   = (const float*)d_in[18];
    const float* b2   = (const float*)d_in[19];
    const float* ln2g = (const float*)d_in[20];
    const float* ln2b = (const float*)d_in[21];
    const float* Wout = (const float*)d_in[22];
    const float* bout = (const float*)d_in[23];
    float* out = (float*)d_out;

    float *tok, *q, *k, *v1, *v2, *o, *hid;
    cudaGetSymbolAddress((void**)&tok, g_tok);
    cudaGetSymbolAddress((void**)&q,   g_q);
    cudaGetSymbolAddress((void**)&k,   g_k);
    cudaGetSymbolAddress((void**)&v1,  g_v1);
    cudaGetSymbolAddress((void**)&v2,  g_v2);
    cudaGetSymbolAddress((void**)&o,   g_o);
    cudaGetSymbolAddress((void**)&hid, g_hid);

    cudaFuncSetAttribute(combine_kernel, cudaFuncAttributeMaxDynamicSharedMemorySize, CMB_SMEM);

    embed_kernel<<<Mm, 128>>>(x, ea, mask, nW, nb, eW, eb, noe);

    for (int l = 0; l < Llay; l++) {
        Ptr8 p;
        p.w[0] = Wq  + (size_t)l*128*128;
        p.w[1] = Wk  + (size_t)l*128*128;
        p.w[2] = Wv1 + (size_t)l*128*128;
        p.w[3] = Wv2 + (size_t)l*128*128;
        p.c[0] = q; p.c[1] = k; p.c[2] = v1; p.c[3] = v2;
        sgemm4_kernel<<<dim3(1, Mm/128, 4), 128>>>(tok, p);

        scores_kernel <<<Bb*Hh*Nn, 256>>>();
        softmax_kernel<<<Bb*Hh*Nn, 256>>>();
        combine_kernel<<<Bb*Hh*(Nn/4), 512, CMB_SMEM>>>();

        // tok = LN(tok + o@Wo + bo)   (fused epilogue)
        sgemm_ln_kernel<<<dim3(1, Mm/128), 128>>>(o, Wo + (size_t)l*128*128, tok,
                                                  bo + l*128, ln1g + l*128, ln1b + l*128, 128);

        // ff
        sgemm_bias_relu_kernel<<<dim3(FFf/128, Mm/128), 128>>>(tok, W1 + (size_t)l*128*512,
                                                               hid, b1 + l*512, 512, 128);
        // tok = LN(tok + hid@W2 + b2) (fused epilogue)
        sgemm_ln_kernel<<<dim3(1, Mm/128), 128>>>(hid, W2 + (size_t)l*512*128, tok,
                                                  b2 + l*128, ln2g + l*128, ln2b + l*128, 512);
    }

    out_kernel<<<Bb*Nn, 128>>>(Wout, bout, out);
}